// round 6
// baseline (speedup 1.0000x reference)
#include <cuda_runtime.h>
#include <cstdint>

typedef unsigned long long ull;

// Problem constants
#define NROWS   16384          // (b*h*w) = 16*32*32
#define NCODES  8192
#define DIMS    256
#define BSTRIDE 262144         // 256*32*32
#define CSTRIDE 1024           // 32*32
#define EMB_OFF 16384
#define EMB_N   4194304
#define LOSS_OFF (16384 + 4194304)
#define GATHER_BLOCKS 512

// GEMM tiling
#define XS_STRIDE 257                       // odd: conflict-free x-tile stores
#define SP        130                       // cst row stride (words), even for LDS.64
#define CST_BUF   (32 * SP)
#define SMEM_WORDS (128 * XS_STRIDE + 2 * CST_BUF)
#define SMEM_BYTES (SMEM_WORDS * 4)

// Scratch (allocation-free: __device__ globals)
__device__ ull    g_best[NROWS];
__device__ float  g_sx[NROWS];
__device__ float  g_se[NCODES];
__device__ float  g_lpart[GATHER_BLOCKS];

// ---------------------------------------------------------------- prep: sx, se, g_best init (one launch)
// blocks [0,64):    sx rows (256 threads each -> 16384 rows) + g_best init
// blocks [64,1088): se rows (8 warps x 1 row -> 8192 rows)
__global__ void prep_kernel(const float* __restrict__ x, const float* __restrict__ cb) {
    if (blockIdx.x < 64) {
        int i = blockIdx.x * 256 + threadIdx.x;
        g_best[i] = 0xFFFFFFFFFFFFFFFFULL;
        const float* p = x + (size_t)(i >> 10) * BSTRIDE + (i & 1023);
        float s = 0.f;
#pragma unroll 8
        for (int c = 0; c < DIMS; c++) { float v = p[(size_t)c * CSTRIDE]; s += v * v; }
        g_sx[i] = s;
    } else {
        int row  = (blockIdx.x - 64) * 8 + (threadIdx.x >> 5);
        int lane = threadIdx.x & 31;
        const float* p = cb + (size_t)row * DIMS;
        float s = 0.f;
#pragma unroll
        for (int k = lane; k < DIMS; k += 32) { float v = p[k]; s += v * v; }
#pragma unroll
        for (int o = 16; o; o >>= 1) s += __shfl_xor_sync(0xFFFFFFFFu, s, o);
        if (lane == 0) g_se[row] = s;
    }
}

// ---------------------------------------------------------------- fused GEMM + argmin
// Bit-exactness contract: each dot product is ONE strictly sequential
// k-ascending fp32 fma chain; dist = fl(fl(se+sx) - 2*dot) (reference formula);
// ties broken by first index. f32x2 lanes carry two independent OUTPUT columns
// (n, n+1), never two k's, so packing does not perturb rounding.
__global__ void __launch_bounds__(256, 1)
gemm_argmin_kernel(const float* __restrict__ x, const float* __restrict__ cb) {
    extern __shared__ float sm[];
    float* xs  = sm;                        // [128][XS_STRIDE] x tile (all 256 dims)
    float* cst = sm + 128 * XS_STRIDE;      // [2][32 k][SP]    codebook chunk, k-major

    const int tid  = threadIdx.x;
    const int rt   = blockIdx.x & 127;      // row tile (128 rows)
    const int cg   = blockIdx.x >> 7;       // code group (1024 codes)
    const int row0 = rt << 7;
    const float* xbase = x + (size_t)(row0 >> 10) * BSTRIDE + (row0 & 1023);

    // ---- x tile: coalesced float4 loads, scalar stores (odd stride, conflict-free)
    {
        int cgrp = tid >> 5;                // warp id: 8 c's per pass
        int q    = tid & 31;                // row quad
        for (int c = cgrp; c < DIMS; c += 8) {
            float4 v = *(const float4*)(xbase + (size_t)c * CSTRIDE + q * 4);
            xs[(q*4+0)*XS_STRIDE + c] = v.x;
            xs[(q*4+1)*XS_STRIDE + c] = v.y;
            xs[(q*4+2)*XS_STRIDE + c] = v.z;
            xs[(q*4+3)*XS_STRIDE + c] = v.w;
        }
    }

    const int tr = tid >> 4;                // row lane  [0,16)
    const int tc = tid & 15;                // col lane  [0,16)
    const int jrow  = tid >> 1;             // staging: code row within tile
    const int khalf = (tid & 1) * 16;       // staging: k half

    float sxv[8];
#pragma unroll
    for (int m = 0; m < 8; m++) sxv[m] = g_sx[row0 + tr + 16*m];

    ull best[8];
#pragma unroll
    for (int m = 0; m < 8; m++) best[m] = 0xFFFFFFFFFFFFFFFFULL;

    // prolog: LDG chunk 0 (code tile 0, k-chunk 0)
    float4 st[4];
    {
        const float4* s = (const float4*)(cb + ((size_t)(cg*1024 + jrow)) * DIMS + khalf);
        st[0] = s[0]; st[1] = s[1]; st[2] = s[2]; st[3] = s[3];
    }

    ull acc[8][4];
#pragma unroll
    for (int m = 0; m < 8; m++)
#pragma unroll
        for (int j = 0; j < 4; j++) acc[m][j] = 0ULL;

    __syncthreads();   // x tile ready

#pragma unroll 1
    for (int c = 0; c < 64; c++) {          // 8 code tiles x 8 k-chunks
        float* tb = cst + (c & 1) * CST_BUF;

        // ---- transpose-store staged chunk: cst[k][code]
#pragma unroll
        for (int q = 0; q < 4; q++) {
            tb[(khalf + 4*q + 0)*SP + jrow] = st[q].x;
            tb[(khalf + 4*q + 1)*SP + jrow] = st[q].y;
            tb[(khalf + 4*q + 2)*SP + jrow] = st[q].z;
            tb[(khalf + 4*q + 3)*SP + jrow] = st[q].w;
        }

        // ---- prefetch next chunk (overlaps this chunk's ~4K-cycle compute)
        if (c < 63) {
            int cn = c + 1;
            const float4* s = (const float4*)(cb +
                ((size_t)(cg*1024 + (cn >> 3)*128 + jrow)) * DIMS + (cn & 7)*32 + khalf);
            st[0] = s[0]; st[1] = s[1]; st[2] = s[2]; st[3] = s[3];
        }
        __syncthreads();                    // tb ready for all

        // ---- compute: 32 k-steps, strictly ascending per accumulator
        const float* bb = tb + 2*tc;
        const int kbase = (c & 7) * 32;
#pragma unroll 2
        for (int kk = 0; kk < 32; kk += 2) {
            ull b0[4], b1[4];
#pragma unroll
            for (int j = 0; j < 4; j++) {
                b0[j] = *(const ull*)(bb + (kk  )*SP + 32*j);
                b1[j] = *(const ull*)(bb + (kk+1)*SP + 32*j);
            }
#pragma unroll
            for (int m = 0; m < 8; m++) {
                float a = xs[(tr + 16*m)*XS_STRIDE + kbase + kk];
                ull a2; asm("mov.b64 %0, {%1, %1};" : "=l"(a2) : "f"(a));
#pragma unroll
                for (int j = 0; j < 4; j++)
                    asm("fma.rn.f32x2 %0, %1, %2, %0;"
                        : "+l"(acc[m][j]) : "l"(a2), "l"(b0[j]));
            }
#pragma unroll
            for (int m = 0; m < 8; m++) {
                float a = xs[(tr + 16*m)*XS_STRIDE + kbase + kk + 1];
                ull a2; asm("mov.b64 %0, {%1, %1};" : "=l"(a2) : "f"(a));
#pragma unroll
                for (int j = 0; j < 4; j++)
                    asm("fma.rn.f32x2 %0, %1, %2, %0;"
                        : "+l"(acc[m][j]) : "l"(a2), "l"(b1[j]));
            }
        }

        // ---- epilogue at end of each code tile
        if ((c & 7) == 7) {
            const int codebase = (cg << 10) + ((c >> 3) << 7);
#pragma unroll
            for (int m = 0; m < 8; m++) {
#pragma unroll
                for (int j = 0; j < 4; j++) {
                    float lo, hi;
                    asm("mov.b64 {%0, %1}, %2;" : "=f"(lo), "=f"(hi) : "l"(acc[m][j]));
                    int n0 = codebase + 2*tc + 32*j;
                    // dist = fl( fl(se+sx) - 2*dot )  == reference rounding
                    float d0 = fmaf(-2.0f, lo, __fadd_rn(g_se[n0],     sxv[m]));
                    float d1 = fmaf(-2.0f, hi, __fadd_rn(g_se[n0 + 1], sxv[m]));
                    ull c0 = ((ull)__float_as_uint(d0) << 32) | (unsigned)n0;
                    ull c1 = ((ull)__float_as_uint(d1) << 32) | (unsigned)(n0 + 1);
                    if (c0 < best[m]) best[m] = c0;
                    if (c1 < best[m]) best[m] = c1;
                    acc[m][j] = 0ULL;
                }
            }
        }
        __syncthreads();                    // all reads of tb done before next STS
    }

    // ---- reduce across the 16 tc lanes of each row, then global atomicMin
#pragma unroll
    for (int m = 0; m < 8; m++) {
        ull p = best[m];
#pragma unroll
        for (int o = 8; o; o >>= 1) {
            ull q = __shfl_xor_sync(0xFFFFFFFFu, p, o);
            if (q < p) p = q;
        }
        if (tc == 0) atomicMin(&g_best[row0 + tr + 16*m], p);
    }
}

// ---------------------------------------------------------------- gather + emb_out + loss partials
__global__ void gather_kernel(const float* __restrict__ x, const float* __restrict__ cb,
                              float* __restrict__ out) {
    __shared__ float es[32 * 257];
    __shared__ int   ids_s[32];
    __shared__ float red[8];
    const int tid = threadIdx.x;
    const int i0  = blockIdx.x << 5;        // 32 rows per block

    if (tid < 32) {
        int id = (int)(unsigned)(g_best[i0 + tid] & 0xFFFFFFFFULL);
        ids_s[tid] = id;
        out[i0 + tid] = (float)id;          // ids, (b,h,w) order == flat i
    }
    __syncthreads();

    for (int q = 0; q < 32; q++)
        es[q * 257 + tid] = cb[(size_t)ids_s[q] * DIMS + tid];
    __syncthreads();

    const int tx = tid & 31, ty = tid >> 5;
    const int b = i0 >> 10, hw0 = i0 & 1023;
    const size_t xoff = (size_t)b * BSTRIDE + hw0 + tx;
    float lsum = 0.f;
#pragma unroll 4
    for (int cc = 0; cc < 32; cc++) {
        int c = ty * 32 + cc;
        float e  = es[tx * 257 + c];
        size_t o = xoff + (size_t)c * CSTRIDE;
        float xv = x[o];
        // straight-through value: fl(x + fl(emb - x))  (NOT exactly emb)
        float dl = __fsub_rn(e, xv);
        out[EMB_OFF + o] = __fadd_rn(xv, dl);
        float d = __fsub_rn(xv, e);
        lsum += d * d;
    }
#pragma unroll
    for (int o = 16; o; o >>= 1) lsum += __shfl_xor_sync(0xFFFFFFFFu, lsum, o);
    if (tx == 0) red[ty] = lsum;
    __syncthreads();
    if (tid == 0) {
        float t = 0.f;
#pragma unroll
        for (int w = 0; w < 8; w++) t += red[w];
        g_lpart[blockIdx.x] = t;            // deterministic: fixed slot per block
    }
}

// Parallel fixed-topology reduction: deterministic across graph replays.
__global__ void fin_kernel(float* __restrict__ out) {
    __shared__ double s[256];
    int t = threadIdx.x;
    s[t] = (double)g_lpart[t] + (double)g_lpart[t + 256];
    __syncthreads();
#pragma unroll
    for (int o = 128; o; o >>= 1) {
        if (t < o) s[t] += s[t + o];
        __syncthreads();
    }
    // dict_loss + 0.25*commitment over identical tensors = 1.25 * MSE
    if (t == 0) out[LOSS_OFF] = (float)(s[0] * 1.25 / (double)EMB_N);
}

// ---------------------------------------------------------------- launch
extern "C" void kernel_launch(void* const* d_in, const int* in_sizes, int n_in,
                              void* d_out, int out_size) {
    const float* x  = (const float*)d_in[0];   // (16,256,32,32) f32
    const float* cb = (const float*)d_in[1];   // (8192,256) f32
    float* out = (float*)d_out;                // [ids 16384 | emb_out 4194304 | loss 1]

    cudaFuncSetAttribute(gemm_argmin_kernel,
                         cudaFuncAttributeMaxDynamicSharedMemorySize, SMEM_BYTES);

    prep_kernel<<<1088, 256>>>(x, cb);
    gemm_argmin_kernel<<<1024, 256, SMEM_BYTES>>>(x, cb);
    gather_kernel<<<GATHER_BLOCKS, 256>>>(x, cb, out);
    fin_kernel<<<1, 256>>>(out);
}